// round 2
// baseline (speedup 1.0000x reference)
#include <cuda_runtime.h>
#include <math.h>

#define EPS_F  1e-8f
#define EPS2_F 1e-16f   // EPS^2, clamp on squared norm so n = d*rsqrt(d) >= EPS

// Per-block partial sums: [6][max_blocks]. Written fully by main kernel each
// launch before finalize reads; no zeroing required.
#define MAX_BLOCKS 16384
__device__ float g_part[6][MAX_BLOCKS];

struct Q4 { float w, x, y, z; };

__device__ __forceinline__ Q4 qmult(const Q4 a, const Q4 b) {
    Q4 r;
    r.w = a.w * b.w - a.x * b.x - a.y * b.y - a.z * b.z;
    r.x = a.w * b.x + a.x * b.w + a.y * b.z - a.z * b.y;
    r.y = a.w * b.y - a.x * b.z + a.y * b.w + a.z * b.x;
    r.z = a.w * b.z + a.x * b.y - a.y * b.x + a.z * b.w;
    return r;
}

// qexp of a 3-vector using MUFU sin/cos; 1/n == rsqrt(d) exactly.
__device__ __forceinline__ Q4 qexp3(float vx, float vy, float vz) {
    float d  = fmaxf(vx * vx + vy * vy + vz * vz, EPS2_F);
    float rn = rsqrtf(d);        // 1/n
    float n  = d * rn;           // n = sqrt(d)
    float s  = __sinf(n) * rn;
    Q4 r;
    r.w = __cosf(n);
    r.x = vx * s; r.y = vy * s; r.z = vz * s;
    return r;
}

__device__ __forceinline__ void qlog3(const Q4 q, float& ox, float& oy, float& oz) {
    float d  = fmaxf(q.x * q.x + q.y * q.y + q.z * q.z, EPS2_F);
    float rn = rsqrtf(d);        // 1/n
    float f  = acosf(fminf(fmaxf(q.w, -1.0f), 1.0f)) * rn;
    ox = q.x * f; oy = q.y * f; oz = q.z * f;
}

__global__ void __launch_bounds__(256) loss_kernel(
    const float* __restrict__ pred,
    const float* __restrict__ targ,
    const float* __restrict__ imu,
    int total /* N*T */)
{
    constexpr int BT = 256;
    constexpr int ROWF = 6;
    constexpr int NSTAGE = (BT + 1) * ROWF;      // 1542 floats
    __shared__ float sp[NSTAGE];                 // pred rows [base .. base+256]
    __shared__ float st[NSTAGE];                 // targ rows
    __shared__ Q4    sq[BT + 1];                 // qexp(targ[...,3:]) per row

    const int tid  = threadIdx.x;
    const int base = blockIdx.x * BT;
    const int total6 = total * 6;

    // ---- Stage 257 rows of pred/targ, coalesced float2 ----
    {
        const float2* psrc = reinterpret_cast<const float2*>(pred + (size_t)base * 6);
        const float2* tsrc = reinterpret_cast<const float2*>(targ + (size_t)base * 6);
        #pragma unroll
        for (int idx = tid; idx < NSTAGE / 2; idx += BT) {
            int gf = base * 6 + idx * 2;
            float2 pv = (gf < total6) ? psrc[idx] : make_float2(0.f, 0.f);
            float2 tv = (gf < total6) ? tsrc[idx] : make_float2(0.f, 0.f);
            sp[idx * 2] = pv.x; sp[idx * 2 + 1] = pv.y;
            st[idx * 2] = tv.x; st[idx * 2 + 1] = tv.y;
        }
    }
    __syncthreads();

    // ---- One qexp per element (shared with the neighbor needing it as q1) ----
    sq[tid] = qexp3(st[tid * ROWF + 3], st[tid * ROWF + 4], st[tid * ROWF + 5]);
    if (tid == 0)
        sq[BT] = qexp3(st[BT * ROWF + 3], st[BT * ROWF + 4], st[BT * ROWF + 5]);
    __syncthreads();

    float s0 = 0.f, s1 = 0.f, s2 = 0.f, s3 = 0.f, s4 = 0.f, s5 = 0.f;

    const int i = base + tid;
    if (i < total) {
        const int t = i & 1023;   // T = 1024

        float p0 = sp[tid*ROWF+0], p1 = sp[tid*ROWF+1], p2 = sp[tid*ROWF+2];
        float p3 = sp[tid*ROWF+3], p4 = sp[tid*ROWF+4], p5 = sp[tid*ROWF+5];
        float g0 = st[tid*ROWF+0], g1 = st[tid*ROWF+1], g2 = st[tid*ROWF+2];
        float g3 = st[tid*ROWF+3], g4 = st[tid*ROWF+4], g5 = st[tid*ROWF+5];

        s0 = fabsf(p0 - g0) + fabsf(p1 - g1) + fabsf(p2 - g2);
        s1 = fabsf(p3 - g3) + fabsf(p4 - g4) + fabsf(p5 - g5);

        if (t < 1023) {
            const int n1 = tid + 1;
            float pp0 = sp[n1*ROWF+0], pp1 = sp[n1*ROWF+1], pp2 = sp[n1*ROWF+2];
            float pp3 = sp[n1*ROWF+3], pp4 = sp[n1*ROWF+4], pp5 = sp[n1*ROWF+5];
            float h0  = st[n1*ROWF+0], h1  = st[n1*ROWF+1], h2  = st[n1*ROWF+2];
            float h3  = st[n1*ROWF+3], h4  = st[n1*ROWF+4], h5  = st[n1*ROWF+5];

            // IMU row i (40B contiguous per thread)
            const float2* im = reinterpret_cast<const float2*>(imu + (size_t)i * 10);
            float2 i01 = im[0], i23 = im[1], i45 = im[2], i67 = im[3], i89 = im[4];
            float ax = i01.x, ay = i01.y, az = i23.x;
            float vx = i23.y, vy = i45.x, vz = i45.y;
            float wx = i67.x, wy = i67.y, wz = i89.x;
            float ts0 = i89.y;
            float ts1 = imu[(size_t)(i + 1) * 10 + 9];

            Q4 q0 = sq[tid];
            Q4 q1 = sq[n1];
            Q4 q0i; q0i.w = q0.w; q0i.x = -q0.x; q0i.y = -q0.y; q0i.z = -q0.z;

            // targ_imu_q = qlog(q0^-1 * q1)
            Q4 rel = qmult(q0i, q1);
            float tiqx, tiqy, tiqz;
            qlog3(rel, tiqx, tiqy, tiqz);

            float dt = (ts1 - ts0) * 1e-9f;
            float itx = vx * dt + 0.5f * ax * dt * dt;
            float ity = vy * dt + 0.5f * ay * dt * dt;
            float itz = vz * dt + 0.5f * az * dt * dt;

            // dq from angular velocity; 1/wn == rsqrt(wd)
            float wd  = fmaxf(wx * wx + wy * wy + wz * wz, EPS2_F);
            float rwn = rsqrtf(wd);
            float wn  = wd * rwn;
            float half = 0.5f * (wn * dt);
            float sfac = __sinf(half) * rwn;
            Q4 dq; dq.w = __cosf(half);
            dq.x = wx * sfac; dq.y = wy * sfac; dq.z = wz * sfac;

            Q4 nq  = qmult(q0, dq);
            Q4 shq = qmult(q0i, nq);
            float iox, ioy, ioz;
            qlog3(shq, iox, ioy, ioz);

            float pvx = pp0 - p0, pvy = pp1 - p1, pvz = pp2 - p2;
            float pqx = pp3 - p3, pqy = pp4 - p4, pqz = pp5 - p5;
            float tvx = h0 - g0,  tvy = h1 - g1,  tvz = h2 - g2;
            float tqx = h3 - g3,  tqy = h4 - g4,  tqz = h5 - g5;

            s2 = fabsf(pvx - tvx) + fabsf(pvy - tvy) + fabsf(pvz - tvz);
            s3 = fabsf(pqx - tqx) + fabsf(pqy - tqy) + fabsf(pqz - tqz);
            s4 = fabsf(pvx - itx) + fabsf(pvy - ity) + fabsf(pvz - itz);
            s5 = fabsf(tiqx - iox) + fabsf(tiqy - ioy) + fabsf(tiqz - ioz);
        }
    }

    // ---- block reduction ----
    const unsigned FULL = 0xffffffffu;
    #pragma unroll
    for (int o = 16; o > 0; o >>= 1) {
        s0 += __shfl_xor_sync(FULL, s0, o);
        s1 += __shfl_xor_sync(FULL, s1, o);
        s2 += __shfl_xor_sync(FULL, s2, o);
        s3 += __shfl_xor_sync(FULL, s3, o);
        s4 += __shfl_xor_sync(FULL, s4, o);
        s5 += __shfl_xor_sync(FULL, s5, o);
    }

    __shared__ float shred[8 * 6];
    int wid  = tid >> 5;
    int lane = tid & 31;
    if (lane == 0) {
        shred[wid * 6 + 0] = s0; shred[wid * 6 + 1] = s1; shred[wid * 6 + 2] = s2;
        shred[wid * 6 + 3] = s3; shred[wid * 6 + 4] = s4; shred[wid * 6 + 5] = s5;
    }
    __syncthreads();
    if (tid == 0) {
        float a0 = 0, a1 = 0, a2 = 0, a3 = 0, a4 = 0, a5 = 0;
        #pragma unroll
        for (int w = 0; w < 8; w++) {
            a0 += shred[w * 6 + 0]; a1 += shred[w * 6 + 1]; a2 += shred[w * 6 + 2];
            a3 += shred[w * 6 + 3]; a4 += shred[w * 6 + 4]; a5 += shred[w * 6 + 5];
        }
        g_part[0][blockIdx.x] = a0; g_part[1][blockIdx.x] = a1;
        g_part[2][blockIdx.x] = a2; g_part[3][blockIdx.x] = a3;
        g_part[4][blockIdx.x] = a4; g_part[5][blockIdx.x] = a5;
    }
}

__global__ void __launch_bounds__(1024) finalize_kernel(
    const float* __restrict__ sax, const float* __restrict__ saq,
    const float* __restrict__ srx, const float* __restrict__ srq,
    float* __restrict__ out, int nb, double inv_abs, double inv_vo)
{
    double a[6] = {0, 0, 0, 0, 0, 0};
    for (int j = threadIdx.x; j < nb; j += 1024) {
        #pragma unroll
        for (int k = 0; k < 6; k++) a[k] += (double)g_part[k][j];
    }
    const unsigned FULL = 0xffffffffu;
    #pragma unroll
    for (int o = 16; o > 0; o >>= 1) {
        #pragma unroll
        for (int k = 0; k < 6; k++) a[k] += __shfl_xor_sync(FULL, a[k], o);
    }
    __shared__ double sh[32][6];
    int wid = threadIdx.x >> 5, lane = threadIdx.x & 31;
    if (lane == 0) {
        #pragma unroll
        for (int k = 0; k < 6; k++) sh[wid][k] = a[k];
    }
    __syncthreads();
    if (threadIdx.x == 0) {
        double m[6] = {0, 0, 0, 0, 0, 0};
        for (int w = 0; w < 32; w++) {
            #pragma unroll
            for (int k = 0; k < 6; k++) m[k] += sh[w][k];
        }
        float m1 = (float)(m[0] * inv_abs);
        float m2 = (float)(m[1] * inv_abs);
        float m3 = (float)(m[2] * inv_vo);
        float m4 = (float)(m[3] * inv_vo);
        float m5 = (float)(m[4] * inv_vo);
        float m6 = (float)(m[5] * inv_vo);

        float A = sax[0], B = saq[0], X = srx[0], Y = srq[0];
        float abs_loss = expf(-A) * m1 + A + expf(-B) * m2 + B;
        float vo_loss  = expf(-X) * m3 + X + expf(-Y) * m4 + Y;
        float imu_loss = expf(-X) * m5 + X + expf(-Y) * m6 + Y;
        out[0] = abs_loss + vo_loss + imu_loss;
    }
}

extern "C" void kernel_launch(void* const* d_in, const int* in_sizes, int n_in,
                              void* d_out, int out_size)
{
    const float* pred = (const float*)d_in[0];
    const float* targ = (const float*)d_in[1];
    const float* imu  = (const float*)d_in[2];
    const float* sax  = (const float*)d_in[3];
    const float* saq  = (const float*)d_in[4];
    const float* srx  = (const float*)d_in[5];
    const float* srq  = (const float*)d_in[6];

    const int T = 1024;
    const int total = in_sizes[0] / 6;          // N*T
    const long long N = total / T;

    int blocks = (total + 255) / 256;
    if (blocks > MAX_BLOCKS) blocks = MAX_BLOCKS;   // safety (inputs fit per reference)
    loss_kernel<<<blocks, 256>>>(pred, targ, imu, total);

    double inv_abs = 1.0 / ((double)total * 3.0);
    double inv_vo  = 1.0 / ((double)N * (double)(T - 1) * 3.0);
    finalize_kernel<<<1, 1024>>>(sax, saq, srx, srq, (float*)d_out, blocks,
                                 inv_abs, inv_vo);
}

// round 3
// speedup vs baseline: 1.0418x; 1.0418x over previous
#include <cuda_runtime.h>
#include <math.h>

#define EPS2_F 1e-16f   // EPS^2: clamp on squared norm so n = d*rsqrt(d) >= 1e-8

// Global accumulators + completion ticket. Zero at module load; the LAST block
// of each launch resets them after consuming, so every graph replay starts
// from zero. No extra kernels, no allocation.
__device__ double   g_acc[6];
__device__ unsigned g_ticket;

struct Q4 { float w, x, y, z; };

__device__ __forceinline__ Q4 qmult(const Q4 a, const Q4 b) {
    Q4 r;
    r.w = a.w * b.w - a.x * b.x - a.y * b.y - a.z * b.z;
    r.x = a.w * b.x + a.x * b.w + a.y * b.z - a.z * b.y;
    r.y = a.w * b.y - a.x * b.z + a.y * b.w + a.z * b.x;
    r.z = a.w * b.z + a.x * b.y - a.y * b.x + a.z * b.w;
    return r;
}

__device__ __forceinline__ Q4 qexp3(float vx, float vy, float vz) {
    float d  = fmaxf(vx * vx + vy * vy + vz * vz, EPS2_F);
    float rn = rsqrtf(d);        // == 1/n
    float n  = d * rn;           // sqrt(d)
    float s  = __sinf(n) * rn;
    Q4 r;
    r.w = __cosf(n);
    r.x = vx * s; r.y = vy * s; r.z = vz * s;
    return r;
}

__device__ __forceinline__ void qlog3(const Q4 q, float& ox, float& oy, float& oz) {
    float d  = fmaxf(q.x * q.x + q.y * q.y + q.z * q.z, EPS2_F);
    float rn = rsqrtf(d);
    float f  = acosf(fminf(fmaxf(q.w, -1.0f), 1.0f)) * rn;
    ox = q.x * f; oy = q.y * f; oz = q.z * f;
}

__global__ void __launch_bounds__(256) loss_kernel(
    const float* __restrict__ pred,
    const float* __restrict__ targ,
    const float* __restrict__ imu,
    const float* __restrict__ sax, const float* __restrict__ saq,
    const float* __restrict__ srx, const float* __restrict__ srq,
    float* __restrict__ out,
    int total, double inv_abs, double inv_vo)
{
    constexpr int BT = 256;
    constexpr int ROWF = 6;
    constexpr int NSTAGE = (BT + 1) * ROWF;      // 1542 floats
    __shared__ float sp[NSTAGE];
    __shared__ float st[NSTAGE];
    __shared__ Q4    sq[BT + 1];

    const int tid  = threadIdx.x;
    const int base = blockIdx.x * BT;
    const int total6 = total * 6;

    // ---- Stage 257 rows of pred/targ (coalesced float2) ----
    {
        const float2* psrc = reinterpret_cast<const float2*>(pred + (size_t)base * 6);
        const float2* tsrc = reinterpret_cast<const float2*>(targ + (size_t)base * 6);
        #pragma unroll
        for (int idx = tid; idx < NSTAGE / 2; idx += BT) {
            int gf = base * 6 + idx * 2;
            float2 pv = (gf < total6) ? psrc[idx] : make_float2(0.f, 0.f);
            float2 tv = (gf < total6) ? tsrc[idx] : make_float2(0.f, 0.f);
            sp[idx * 2] = pv.x; sp[idx * 2 + 1] = pv.y;
            st[idx * 2] = tv.x; st[idx * 2 + 1] = tv.y;
        }
    }
    __syncthreads();

    // ---- One qexp per element, shared via smem ----
    sq[tid] = qexp3(st[tid * ROWF + 3], st[tid * ROWF + 4], st[tid * ROWF + 5]);
    if (tid == 0)
        sq[BT] = qexp3(st[BT * ROWF + 3], st[BT * ROWF + 4], st[BT * ROWF + 5]);
    __syncthreads();

    float s0 = 0.f, s1 = 0.f, s2 = 0.f, s3 = 0.f, s4 = 0.f, s5 = 0.f;

    const int i = base + tid;
    if (i < total) {
        const int t = i & 1023;   // T = 1024

        float p0 = sp[tid*ROWF+0], p1 = sp[tid*ROWF+1], p2 = sp[tid*ROWF+2];
        float p3 = sp[tid*ROWF+3], p4 = sp[tid*ROWF+4], p5 = sp[tid*ROWF+5];
        float g0 = st[tid*ROWF+0], g1 = st[tid*ROWF+1], g2 = st[tid*ROWF+2];
        float g3 = st[tid*ROWF+3], g4 = st[tid*ROWF+4], g5 = st[tid*ROWF+5];

        s0 = fabsf(p0 - g0) + fabsf(p1 - g1) + fabsf(p2 - g2);
        s1 = fabsf(p3 - g3) + fabsf(p4 - g4) + fabsf(p5 - g5);

        if (t < 1023) {
            const int n1 = tid + 1;
            float pp0 = sp[n1*ROWF+0], pp1 = sp[n1*ROWF+1], pp2 = sp[n1*ROWF+2];
            float pp3 = sp[n1*ROWF+3], pp4 = sp[n1*ROWF+4], pp5 = sp[n1*ROWF+5];
            float h0  = st[n1*ROWF+0], h1  = st[n1*ROWF+1], h2  = st[n1*ROWF+2];
            float h3  = st[n1*ROWF+3], h4  = st[n1*ROWF+4], h5  = st[n1*ROWF+5];

            const float2* im = reinterpret_cast<const float2*>(imu + (size_t)i * 10);
            float2 i01 = im[0], i23 = im[1], i45 = im[2], i67 = im[3], i89 = im[4];
            float ax = i01.x, ay = i01.y, az = i23.x;
            float vx = i23.y, vy = i45.x, vz = i45.y;
            float wx = i67.x, wy = i67.y, wz = i89.x;
            float ts0 = i89.y;
            float ts1 = imu[(size_t)(i + 1) * 10 + 9];

            Q4 q0 = sq[tid];
            Q4 q1 = sq[n1];
            Q4 q0i; q0i.w = q0.w; q0i.x = -q0.x; q0i.y = -q0.y; q0i.z = -q0.z;

            Q4 rel = qmult(q0i, q1);
            float tiqx, tiqy, tiqz;
            qlog3(rel, tiqx, tiqy, tiqz);

            float dt = (ts1 - ts0) * 1e-9f;
            float itx = vx * dt + 0.5f * ax * dt * dt;
            float ity = vy * dt + 0.5f * ay * dt * dt;
            float itz = vz * dt + 0.5f * az * dt * dt;

            float wd  = fmaxf(wx * wx + wy * wy + wz * wz, EPS2_F);
            float rwn = rsqrtf(wd);
            float wn  = wd * rwn;
            float half = 0.5f * (wn * dt);
            float sfac = __sinf(half) * rwn;
            Q4 dq; dq.w = __cosf(half);
            dq.x = wx * sfac; dq.y = wy * sfac; dq.z = wz * sfac;

            Q4 nq  = qmult(q0, dq);
            Q4 shq = qmult(q0i, nq);
            float iox, ioy, ioz;
            qlog3(shq, iox, ioy, ioz);

            float pvx = pp0 - p0, pvy = pp1 - p1, pvz = pp2 - p2;
            float pqx = pp3 - p3, pqy = pp4 - p4, pqz = pp5 - p5;
            float tvx = h0 - g0,  tvy = h1 - g1,  tvz = h2 - g2;
            float tqx = h3 - g3,  tqy = h4 - g4,  tqz = h5 - g5;

            s2 = fabsf(pvx - tvx) + fabsf(pvy - tvy) + fabsf(pvz - tvz);
            s3 = fabsf(pqx - tqx) + fabsf(pqy - tqy) + fabsf(pqz - tqz);
            s4 = fabsf(pvx - itx) + fabsf(pvy - ity) + fabsf(pvz - itz);
            s5 = fabsf(tiqx - iox) + fabsf(tiqy - ioy) + fabsf(tiqz - ioz);
        }
    }

    // ---- block reduction ----
    const unsigned FULL = 0xffffffffu;
    #pragma unroll
    for (int o = 16; o > 0; o >>= 1) {
        s0 += __shfl_xor_sync(FULL, s0, o);
        s1 += __shfl_xor_sync(FULL, s1, o);
        s2 += __shfl_xor_sync(FULL, s2, o);
        s3 += __shfl_xor_sync(FULL, s3, o);
        s4 += __shfl_xor_sync(FULL, s4, o);
        s5 += __shfl_xor_sync(FULL, s5, o);
    }

    __shared__ float shred[8 * 6];
    __shared__ bool  is_last;
    int wid  = tid >> 5;
    int lane = tid & 31;
    if (lane == 0) {
        shred[wid * 6 + 0] = s0; shred[wid * 6 + 1] = s1; shred[wid * 6 + 2] = s2;
        shred[wid * 6 + 3] = s3; shred[wid * 6 + 4] = s4; shred[wid * 6 + 5] = s5;
    }
    __syncthreads();

    if (tid == 0) {
        float a0 = 0, a1 = 0, a2 = 0, a3 = 0, a4 = 0, a5 = 0;
        #pragma unroll
        for (int w = 0; w < 8; w++) {
            a0 += shred[w * 6 + 0]; a1 += shred[w * 6 + 1]; a2 += shred[w * 6 + 2];
            a3 += shred[w * 6 + 3]; a4 += shred[w * 6 + 4]; a5 += shred[w * 6 + 5];
        }
        atomicAdd(&g_acc[0], (double)a0); atomicAdd(&g_acc[1], (double)a1);
        atomicAdd(&g_acc[2], (double)a2); atomicAdd(&g_acc[3], (double)a3);
        atomicAdd(&g_acc[4], (double)a4); atomicAdd(&g_acc[5], (double)a5);
        __threadfence();
        unsigned ticket = atomicAdd(&g_ticket, 1u);
        is_last = (ticket == gridDim.x - 1);
    }
    __syncthreads();

    // ---- last block finalizes and resets state for the next replay ----
    if (is_last && tid == 0) {
        __threadfence();   // acquire: all g_acc atomics are visible
        double m0 = g_acc[0], m1d = g_acc[1], m2d = g_acc[2];
        double m3d = g_acc[3], m4d = g_acc[4], m5d = g_acc[5];

        float m1 = (float)(m0  * inv_abs);
        float m2 = (float)(m1d * inv_abs);
        float m3 = (float)(m2d * inv_vo);
        float m4 = (float)(m3d * inv_vo);
        float m5 = (float)(m4d * inv_vo);
        float m6 = (float)(m5d * inv_vo);

        float A = sax[0], B = saq[0], X = srx[0], Y = srq[0];
        float abs_loss = expf(-A) * m1 + A + expf(-B) * m2 + B;
        float vo_loss  = expf(-X) * m3 + X + expf(-Y) * m4 + Y;
        float imu_loss = expf(-X) * m5 + X + expf(-Y) * m6 + Y;
        out[0] = abs_loss + vo_loss + imu_loss;

        // reset for next graph replay
        g_acc[0] = 0.0; g_acc[1] = 0.0; g_acc[2] = 0.0;
        g_acc[3] = 0.0; g_acc[4] = 0.0; g_acc[5] = 0.0;
        g_ticket = 0u;
        __threadfence();
    }
}

extern "C" void kernel_launch(void* const* d_in, const int* in_sizes, int n_in,
                              void* d_out, int out_size)
{
    const float* pred = (const float*)d_in[0];
    const float* targ = (const float*)d_in[1];
    const float* imu  = (const float*)d_in[2];
    const float* sax  = (const float*)d_in[3];
    const float* saq  = (const float*)d_in[4];
    const float* srx  = (const float*)d_in[5];
    const float* srq  = (const float*)d_in[6];

    const int T = 1024;
    const int total = in_sizes[0] / 6;          // N*T
    const long long N = total / T;

    int blocks = (total + 255) / 256;

    double inv_abs = 1.0 / ((double)total * 3.0);
    double inv_vo  = 1.0 / ((double)N * (double)(T - 1) * 3.0);

    loss_kernel<<<blocks, 256>>>(pred, targ, imu, sax, saq, srx, srq,
                                 (float*)d_out, total, inv_abs, inv_vo);
}

// round 4
// speedup vs baseline: 1.2418x; 1.1920x over previous
#include <cuda_runtime.h>
#include <math.h>

#define EPS2_F 1e-16f   // EPS^2: clamp squared norm so n = d*rsqrt(d) >= 1e-8

// Global accumulators + completion ticket. Zero at module load; the LAST block
// of each launch resets them, so every graph replay starts from zero.
__device__ double   g_acc[6];
__device__ unsigned g_ticket;

struct Q4 { float w, x, y, z; };

__device__ __forceinline__ Q4 qmult(const Q4 a, const Q4 b) {
    Q4 r;
    r.w = a.w * b.w - a.x * b.x - a.y * b.y - a.z * b.z;
    r.x = a.w * b.x + a.x * b.w + a.y * b.z - a.z * b.y;
    r.y = a.w * b.y - a.x * b.z + a.y * b.w + a.z * b.x;
    r.z = a.w * b.z + a.x * b.y - a.y * b.x + a.z * b.w;
    return r;
}

__device__ __forceinline__ Q4 qexp3(float vx, float vy, float vz) {
    float d  = fmaxf(vx * vx + vy * vy + vz * vz, EPS2_F);
    float rn = rsqrtf(d);        // == 1/n
    float n  = d * rn;           // sqrt(d)
    float s  = __sinf(n) * rn;
    Q4 r;
    r.w = __cosf(n);
    r.x = vx * s; r.y = vy * s; r.z = vz * s;
    return r;
}

__device__ __forceinline__ void qlog3(const Q4 q, float& ox, float& oy, float& oz) {
    float d  = fmaxf(q.x * q.x + q.y * q.y + q.z * q.z, EPS2_F);
    float rn = rsqrtf(d);
    float f  = acosf(fminf(fmaxf(q.w, -1.0f), 1.0f)) * rn;
    ox = q.x * f; oy = q.y * f; oz = q.z * f;
}

__global__ void __launch_bounds__(256) loss_kernel(
    const float* __restrict__ pred,
    const float* __restrict__ targ,
    const float* __restrict__ imu,
    const float* __restrict__ sax, const float* __restrict__ saq,
    const float* __restrict__ srx, const float* __restrict__ srq,
    float* __restrict__ out,
    int total, double inv_abs, double inv_vo)
{
    const int tid = threadIdx.x;
    const int i   = blockIdx.x * 256 + tid;

    float s0 = 0.f, s1 = 0.f, s2 = 0.f, s3 = 0.f, s4 = 0.f, s5 = 0.f;

    if (i < total) {
        const int t = i & 1023;   // T = 1024

        const float2* pr = reinterpret_cast<const float2*>(pred + (size_t)i * 6);
        const float2* tg = reinterpret_cast<const float2*>(targ + (size_t)i * 6);
        float2 pA = pr[0], pB = pr[1], pC = pr[2];
        float2 gA = tg[0], gB = tg[1], gC = tg[2];
        float p0 = pA.x, p1 = pA.y, p2 = pB.x, p3 = pB.y, p4 = pC.x, p5 = pC.y;
        float g0 = gA.x, g1 = gA.y, g2 = gB.x, g3 = gB.y, g4 = gC.x, g5 = gC.y;

        s0 = fabsf(p0 - g0) + fabsf(p1 - g1) + fabsf(p2 - g2);
        s1 = fabsf(p3 - g3) + fabsf(p4 - g4) + fabsf(p5 - g5);

        if (t < 1023) {
            // Neighbor rows: DRAM lines already touched by the next thread; L1/L2 hits.
            const float2* pr1 = reinterpret_cast<const float2*>(pred + (size_t)(i + 1) * 6);
            const float2* tg1 = reinterpret_cast<const float2*>(targ + (size_t)(i + 1) * 6);
            float2 qA = pr1[0], qB = pr1[1], qC = pr1[2];
            float2 hA = tg1[0], hB = tg1[1], hC = tg1[2];
            float pp0 = qA.x, pp1 = qA.y, pp2 = qB.x, pp3 = qB.y, pp4 = qC.x, pp5 = qC.y;
            float h0  = hA.x, h1  = hA.y, h2  = hB.x, h3  = hB.y, h4  = hC.x, h5  = hC.y;

            const float2* im = reinterpret_cast<const float2*>(imu + (size_t)i * 10);
            float2 i01 = im[0], i23 = im[1], i45 = im[2], i67 = im[3], i89 = im[4];
            float ax = i01.x, ay = i01.y, az = i23.x;
            float vx = i23.y, vy = i45.x, vz = i45.y;
            float wx = i67.x, wy = i67.y, wz = i89.x;
            float ts0 = i89.y;
            float ts1 = imu[(size_t)(i + 1) * 10 + 9];

            // qexp recomputed per thread — MUFU is far cheaper than smem sharing.
            Q4 q0 = qexp3(g3, g4, g5);
            Q4 q1 = qexp3(h3, h4, h5);
            Q4 q0i; q0i.w = q0.w; q0i.x = -q0.x; q0i.y = -q0.y; q0i.z = -q0.z;

            Q4 rel = qmult(q0i, q1);
            float tiqx, tiqy, tiqz;
            qlog3(rel, tiqx, tiqy, tiqz);

            float dt = (ts1 - ts0) * 1e-9f;
            float itx = vx * dt + 0.5f * ax * dt * dt;
            float ity = vy * dt + 0.5f * ay * dt * dt;
            float itz = vz * dt + 0.5f * az * dt * dt;

            float wd  = fmaxf(wx * wx + wy * wy + wz * wz, EPS2_F);
            float rwn = rsqrtf(wd);
            float wn  = wd * rwn;
            float half = 0.5f * (wn * dt);
            float sfac = __sinf(half) * rwn;
            Q4 dq; dq.w = __cosf(half);
            dq.x = wx * sfac; dq.y = wy * sfac; dq.z = wz * sfac;

            Q4 nq  = qmult(q0, dq);
            Q4 shq = qmult(q0i, nq);
            float iox, ioy, ioz;
            qlog3(shq, iox, ioy, ioz);

            float pvx = pp0 - p0, pvy = pp1 - p1, pvz = pp2 - p2;
            float pqx = pp3 - p3, pqy = pp4 - p4, pqz = pp5 - p5;
            float tvx = h0 - g0,  tvy = h1 - g1,  tvz = h2 - g2;
            float tqx = h3 - g3,  tqy = h4 - g4,  tqz = h5 - g5;

            s2 = fabsf(pvx - tvx) + fabsf(pvy - tvy) + fabsf(pvz - tvz);
            s3 = fabsf(pqx - tqx) + fabsf(pqy - tqy) + fabsf(pqz - tqz);
            s4 = fabsf(pvx - itx) + fabsf(pvy - ity) + fabsf(pvz - itz);
            s5 = fabsf(tiqx - iox) + fabsf(tiqy - ioy) + fabsf(tiqz - ioz);
        }
    }

    // ---- block reduction ----
    const unsigned FULL = 0xffffffffu;
    #pragma unroll
    for (int o = 16; o > 0; o >>= 1) {
        s0 += __shfl_xor_sync(FULL, s0, o);
        s1 += __shfl_xor_sync(FULL, s1, o);
        s2 += __shfl_xor_sync(FULL, s2, o);
        s3 += __shfl_xor_sync(FULL, s3, o);
        s4 += __shfl_xor_sync(FULL, s4, o);
        s5 += __shfl_xor_sync(FULL, s5, o);
    }

    __shared__ float shred[8 * 6];
    __shared__ bool  is_last;
    int wid  = tid >> 5;
    int lane = tid & 31;
    if (lane == 0) {
        shred[wid * 6 + 0] = s0; shred[wid * 6 + 1] = s1; shred[wid * 6 + 2] = s2;
        shred[wid * 6 + 3] = s3; shred[wid * 6 + 4] = s4; shred[wid * 6 + 5] = s5;
    }
    __syncthreads();

    if (tid == 0) {
        float a0 = 0, a1 = 0, a2 = 0, a3 = 0, a4 = 0, a5 = 0;
        #pragma unroll
        for (int w = 0; w < 8; w++) {
            a0 += shred[w * 6 + 0]; a1 += shred[w * 6 + 1]; a2 += shred[w * 6 + 2];
            a3 += shred[w * 6 + 3]; a4 += shred[w * 6 + 4]; a5 += shred[w * 6 + 5];
        }
        atomicAdd(&g_acc[0], (double)a0); atomicAdd(&g_acc[1], (double)a1);
        atomicAdd(&g_acc[2], (double)a2); atomicAdd(&g_acc[3], (double)a3);
        atomicAdd(&g_acc[4], (double)a4); atomicAdd(&g_acc[5], (double)a5);
        __threadfence();
        unsigned ticket = atomicAdd(&g_ticket, 1u);
        is_last = (ticket == gridDim.x - 1);
    }
    __syncthreads();

    if (is_last && tid == 0) {
        __threadfence();
        double m0 = g_acc[0], m1d = g_acc[1], m2d = g_acc[2];
        double m3d = g_acc[3], m4d = g_acc[4], m5d = g_acc[5];

        float m1 = (float)(m0  * inv_abs);
        float m2 = (float)(m1d * inv_abs);
        float m3 = (float)(m2d * inv_vo);
        float m4 = (float)(m3d * inv_vo);
        float m5 = (float)(m4d * inv_vo);
        float m6 = (float)(m5d * inv_vo);

        float A = sax[0], B = saq[0], X = srx[0], Y = srq[0];
        float abs_loss = expf(-A) * m1 + A + expf(-B) * m2 + B;
        float vo_loss  = expf(-X) * m3 + X + expf(-Y) * m4 + Y;
        float imu_loss = expf(-X) * m5 + X + expf(-Y) * m6 + Y;
        out[0] = abs_loss + vo_loss + imu_loss;

        g_acc[0] = 0.0; g_acc[1] = 0.0; g_acc[2] = 0.0;
        g_acc[3] = 0.0; g_acc[4] = 0.0; g_acc[5] = 0.0;
        g_ticket = 0u;
        __threadfence();
    }
}

extern "C" void kernel_launch(void* const* d_in, const int* in_sizes, int n_in,
                              void* d_out, int out_size)
{
    const float* pred = (const float*)d_in[0];
    const float* targ = (const float*)d_in[1];
    const float* imu  = (const float*)d_in[2];
    const float* sax  = (const float*)d_in[3];
    const float* saq  = (const float*)d_in[4];
    const float* srx  = (const float*)d_in[5];
    const float* srq  = (const float*)d_in[6];

    const int T = 1024;
    const int total = in_sizes[0] / 6;          // N*T
    const long long N = total / T;

    int blocks = (total + 255) / 256;

    double inv_abs = 1.0 / ((double)total * 3.0);
    double inv_vo  = 1.0 / ((double)N * (double)(T - 1) * 3.0);

    loss_kernel<<<blocks, 256>>>(pred, targ, imu, sax, saq, srx, srq,
                                 (float*)d_out, total, inv_abs, inv_vo);
}

// round 7
// speedup vs baseline: 1.8805x; 1.5143x over previous
#include <cuda_runtime.h>
#include <math.h>

#define EPS2_F 1e-16f   /* EPS^2: clamp squared norm so n = d*rsqrt(d) >= 1e-8 */

// Global accumulators + completion ticket. Zero at module load; the LAST block
// resets them each launch, so every graph replay starts from zero.
__device__ double   g_acc[6];
__device__ unsigned g_ticket;

struct Q4 { float w, x, y, z; };
struct Row { float f[6]; };

__device__ __forceinline__ Q4 qmult(const Q4 a, const Q4 b) {
    Q4 r;
    r.w = a.w * b.w - a.x * b.x - a.y * b.y - a.z * b.z;
    r.x = a.w * b.x + a.x * b.w + a.y * b.z - a.z * b.y;
    r.y = a.w * b.y - a.x * b.z + a.y * b.w + a.z * b.x;
    r.z = a.w * b.z + a.x * b.y - a.y * b.x + a.z * b.w;
    return r;
}

__device__ __forceinline__ Q4 qexp3(float vx, float vy, float vz) {
    float d  = fmaxf(vx * vx + vy * vy + vz * vz, EPS2_F);
    float rn = rsqrtf(d);        // == 1/n
    float n  = d * rn;           // sqrt(d)
    float s  = __sinf(n) * rn;
    Q4 r;
    r.w = __cosf(n);
    r.x = vx * s; r.y = vy * s; r.z = vz * s;
    return r;
}

__device__ __forceinline__ void qlog3(const Q4 q, float& ox, float& oy, float& oz) {
    float d  = fmaxf(q.x * q.x + q.y * q.y + q.z * q.z, EPS2_F);
    float rn = rsqrtf(d);
    float f  = acosf(fminf(fmaxf(q.w, -1.0f), 1.0f)) * rn;
    ox = q.x * f; oy = q.y * f; oz = q.z * f;
}

// One (t -> t+1) VO + IMU contribution.
__device__ __forceinline__ void vo_term(
    const Row& p0, const Row& p1, const Row& g0, const Row& g1,
    float ax, float ay, float az, float vx, float vy, float vz,
    float wx, float wy, float wz, float ts0, float ts1,
    const Q4& q0, const Q4& q1,
    float& s2, float& s3, float& s4, float& s5)
{
    Q4 q0i; q0i.w = q0.w; q0i.x = -q0.x; q0i.y = -q0.y; q0i.z = -q0.z;

    // targ_imu_q = qlog(q0^-1 * q1)
    Q4 rel = qmult(q0i, q1);
    float tiqx, tiqy, tiqz;
    qlog3(rel, tiqx, tiqy, tiqz);

    float dt = (ts1 - ts0) * 1e-9f;
    float itx = vx * dt + 0.5f * ax * dt * dt;
    float ity = vy * dt + 0.5f * ay * dt * dt;
    float itz = vz * dt + 0.5f * az * dt * dt;

    float wd  = fmaxf(wx * wx + wy * wy + wz * wz, EPS2_F);
    float rwn = rsqrtf(wd);
    float wn  = wd * rwn;
    float half = 0.5f * (wn * dt);
    float sfac = __sinf(half) * rwn;
    Q4 dq; dq.w = __cosf(half);
    dq.x = wx * sfac; dq.y = wy * sfac; dq.z = wz * sfac;

    Q4 nq  = qmult(q0, dq);
    Q4 shq = qmult(q0i, nq);
    float iox, ioy, ioz;
    qlog3(shq, iox, ioy, ioz);

    float pvx = p1.f[0] - p0.f[0], pvy = p1.f[1] - p0.f[1], pvz = p1.f[2] - p0.f[2];
    float pqx = p1.f[3] - p0.f[3], pqy = p1.f[4] - p0.f[4], pqz = p1.f[5] - p0.f[5];
    float tvx = g1.f[0] - g0.f[0], tvy = g1.f[1] - g0.f[1], tvz = g1.f[2] - g0.f[2];
    float tqx = g1.f[3] - g0.f[3], tqy = g1.f[4] - g0.f[4], tqz = g1.f[5] - g0.f[5];

    s2 += fabsf(pvx - tvx) + fabsf(pvy - tvy) + fabsf(pvz - tvz);
    s3 += fabsf(pqx - tqx) + fabsf(pqy - tqy) + fabsf(pqz - tqz);
    s4 += fabsf(pvx - itx) + fabsf(pvy - ity) + fabsf(pvz - itz);
    s5 += fabsf(tiqx - iox) + fabsf(tiqy - ioy) + fabsf(tiqz - ioz);
}

__global__ void __launch_bounds__(256) loss_kernel(
    const float* __restrict__ pred,
    const float* __restrict__ targ,
    const float* __restrict__ imu,
    const float* __restrict__ sax, const float* __restrict__ saq,
    const float* __restrict__ srx, const float* __restrict__ srq,
    float* __restrict__ out,
    int npairs, double inv_abs, double inv_vo)
{
    const int tid = threadIdx.x;
    const int j   = blockIdx.x * 256 + tid;    // pair index: rows 2j, 2j+1

    float s0 = 0.f, s1 = 0.f, s2 = 0.f, s3 = 0.f, s4 = 0.f, s5 = 0.f;

    if (j < npairs) {
        // pred/targ rows 2j..2j+1: 12 floats = 3 x float4, 16B-aligned (48j % 16 == 0)
        const float4* p4 = reinterpret_cast<const float4*>(pred) + (size_t)3 * j;
        const float4* t4 = reinterpret_cast<const float4*>(targ) + (size_t)3 * j;
        float4 pa = p4[0], pb = p4[1], pc = p4[2];
        float4 ta = t4[0], tb = t4[1], tc = t4[2];

        // imu rows 2j..2j+1: 20 floats = 5 x float4 (80j % 16 == 0)
        const float4* i4 = reinterpret_cast<const float4*>(imu) + (size_t)5 * j;
        float4 ia = i4[0], ib = i4[1], ic = i4[2], id4 = i4[3], ie4 = i4[4];

        const int t1  = (2 * j + 1) & 1023;    // T = 1024
        const bool has2 = (t1 != 1023);

        Row p0 = {{pa.x, pa.y, pa.z, pa.w, pb.x, pb.y}};
        Row p1 = {{pb.z, pb.w, pc.x, pc.y, pc.z, pc.w}};
        Row g0 = {{ta.x, ta.y, ta.z, ta.w, tb.x, tb.y}};
        Row g1 = {{tb.z, tb.w, tc.x, tc.y, tc.z, tc.w}};

        Row p2, g2; float ts2 = 0.f;
        if (has2) {
            // row 2j+2: floats [12j+12, 12j+18) -> float4 + float2, both aligned
            float4 pdq = p4[3];
            float2 pe2 = reinterpret_cast<const float2*>(pred)[(size_t)6 * j + 8];
            float4 tdq = t4[3];
            float2 te2 = reinterpret_cast<const float2*>(targ)[(size_t)6 * j + 8];
            p2 = {{pdq.x, pdq.y, pdq.z, pdq.w, pe2.x, pe2.y}};
            g2 = {{tdq.x, tdq.y, tdq.z, tdq.w, te2.x, te2.y}};
            ts2 = imu[(size_t)20 * j + 29];    // ts of row 2j+2
        }

        // abs loss for both rows
        s0 = fabsf(p0.f[0]-g0.f[0]) + fabsf(p0.f[1]-g0.f[1]) + fabsf(p0.f[2]-g0.f[2])
           + fabsf(p1.f[0]-g1.f[0]) + fabsf(p1.f[1]-g1.f[1]) + fabsf(p1.f[2]-g1.f[2]);
        s1 = fabsf(p0.f[3]-g0.f[3]) + fabsf(p0.f[4]-g0.f[4]) + fabsf(p0.f[5]-g0.f[5])
           + fabsf(p1.f[3]-g1.f[3]) + fabsf(p1.f[4]-g1.f[4]) + fabsf(p1.f[5]-g1.f[5]);

        // qexp: 3 per pair (middle one shared between the two vo terms)
        Q4 qe0 = qexp3(g0.f[3], g0.f[4], g0.f[5]);
        Q4 qe1 = qexp3(g1.f[3], g1.f[4], g1.f[5]);

        // element 2j -> 2j+1  (t even, always < 1023)
        // imu row 2j   = {ia.x,ia.y,ia.z, ia.w,ib.x,ib.y, ib.z,ib.w,ic.x, ic.y}
        // imu row 2j+1 = {ic.z,ic.w,id4.x, id4.y,id4.z,id4.w, ie4.x,ie4.y,ie4.z, ie4.w}
        vo_term(p0, p1, g0, g1,
                ia.x, ia.y, ia.z,        // accel
                ia.w, ib.x, ib.y,        // vel
                ib.z, ib.w, ic.x,        // ang_vel
                ic.y, ie4.w,             // ts0 = row0[9], ts1 = row1[9]
                qe0, qe1, s2, s3, s4, s5);

        if (has2) {
            Q4 qe2 = qexp3(g2.f[3], g2.f[4], g2.f[5]);
            // element 2j+1 -> 2j+2; imu row 2j+1
            vo_term(p1, p2, g1, g2,
                    ic.z, ic.w, id4.x,   // accel
                    id4.y, id4.z, id4.w, // vel
                    ie4.x, ie4.y, ie4.z, // ang_vel
                    ie4.w, ts2,          // ts1 = row1[9], ts2 = row2[9]
                    qe1, qe2, s2, s3, s4, s5);
        }
    }

    // ---- block reduction ----
    const unsigned FULL = 0xffffffffu;
    #pragma unroll
    for (int o = 16; o > 0; o >>= 1) {
        s0 += __shfl_xor_sync(FULL, s0, o);
        s1 += __shfl_xor_sync(FULL, s1, o);
        s2 += __shfl_xor_sync(FULL, s2, o);
        s3 += __shfl_xor_sync(FULL, s3, o);
        s4 += __shfl_xor_sync(FULL, s4, o);
        s5 += __shfl_xor_sync(FULL, s5, o);
    }

    __shared__ float shred[8 * 6];
    __shared__ bool  is_last;
    int wid  = tid >> 5;
    int lane = tid & 31;
    if (lane == 0) {
        shred[wid * 6 + 0] = s0; shred[wid * 6 + 1] = s1; shred[wid * 6 + 2] = s2;
        shred[wid * 6 + 3] = s3; shred[wid * 6 + 4] = s4; shred[wid * 6 + 5] = s5;
    }
    __syncthreads();

    if (tid == 0) {
        float a0 = 0, a1 = 0, a2 = 0, a3 = 0, a4 = 0, a5 = 0;
        #pragma unroll
        for (int w = 0; w < 8; w++) {
            a0 += shred[w * 6 + 0]; a1 += shred[w * 6 + 1]; a2 += shred[w * 6 + 2];
            a3 += shred[w * 6 + 3]; a4 += shred[w * 6 + 4]; a5 += shred[w * 6 + 5];
        }
        atomicAdd(&g_acc[0], (double)a0); atomicAdd(&g_acc[1], (double)a1);
        atomicAdd(&g_acc[2], (double)a2); atomicAdd(&g_acc[3], (double)a3);
        atomicAdd(&g_acc[4], (double)a4); atomicAdd(&g_acc[5], (double)a5);
        __threadfence();
        unsigned ticket = atomicAdd(&g_ticket, 1u);
        is_last = (ticket == gridDim.x - 1);
    }
    __syncthreads();

    if (is_last && tid == 0) {
        __threadfence();
        double m0 = g_acc[0], m1d = g_acc[1], m2d = g_acc[2];
        double m3d = g_acc[3], m4d = g_acc[4], m5d = g_acc[5];

        float m1 = (float)(m0  * inv_abs);
        float m2 = (float)(m1d * inv_abs);
        float m3 = (float)(m2d * inv_vo);
        float m4 = (float)(m3d * inv_vo);
        float m5 = (float)(m4d * inv_vo);
        float m6 = (float)(m5d * inv_vo);

        float A = sax[0], B = saq[0], X = srx[0], Y = srq[0];
        float abs_loss = expf(-A) * m1 + A + expf(-B) * m2 + B;
        float vo_loss  = expf(-X) * m3 + X + expf(-Y) * m4 + Y;
        float imu_loss = expf(-X) * m5 + X + expf(-Y) * m6 + Y;
        out[0] = abs_loss + vo_loss + imu_loss;

        g_acc[0] = 0.0; g_acc[1] = 0.0; g_acc[2] = 0.0;
        g_acc[3] = 0.0; g_acc[4] = 0.0; g_acc[5] = 0.0;
        g_ticket = 0u;
        __threadfence();
    }
}

extern "C" void kernel_launch(void* const* d_in, const int* in_sizes, int n_in,
                              void* d_out, int out_size)
{
    const float* pred = (const float*)d_in[0];
    const float* targ = (const float*)d_in[1];
    const float* imu  = (const float*)d_in[2];
    const float* sax  = (const float*)d_in[3];
    const float* saq  = (const float*)d_in[4];
    const float* srx  = (const float*)d_in[5];
    const float* srq  = (const float*)d_in[6];

    const int T = 1024;
    const int total = in_sizes[0] / 6;          // N*T (even)
    const long long N = total / T;
    const int npairs = total >> 1;

    int blocks = (npairs + 255) / 256;

    double inv_abs = 1.0 / ((double)total * 3.0);
    double inv_vo  = 1.0 / ((double)N * (double)(T - 1) * 3.0);

    loss_kernel<<<blocks, 256>>>(pred, targ, imu, sax, saq, srx, srq,
                                 (float*)d_out, npairs, inv_abs, inv_vo);
}